// round 4
// baseline (speedup 1.0000x reference)
#include <cuda_runtime.h>
#include <math.h>

#define T_TOK 16
#define NU    4096
#define E     128
#define H     128
#define LP    32
#define NP    1024
#define G4    512   // 4*H

// ---------------- scratch (static device memory; allocation-free) ----------------
__device__ __align__(16) float g_gpre_f[(size_t)T_TOK*NU*G4];
__device__ __align__(16) float g_gpre_b[(size_t)T_TOK*NU*G4];
__device__ __align__(16) float g_hf[(size_t)T_TOK*NU*H];
__device__ __align__(16) float g_hb[(size_t)T_TOK*NU*H];
__device__ __align__(16) float g_cf[NU*H];
__device__ __align__(16) float g_cb[NU*H];
__device__ __align__(16) float g_hcat[(size_t)T_TOK*NU*2*H];
__device__ __align__(16) float g_outlin[(size_t)T_TOK*NU*E];
__device__ __align__(16) float g_tokfeat[NU*E];
__device__ int   g_toklen[NU];
__device__ int   g_rm_tb[T_TOK*NU];
__device__ int   g_rm_pf[LP*NP];
__device__ int   g_rm_pb[LP*NP];
__device__ int   g_plen[NP];
__device__ __align__(16) float g_gpre_pf[(size_t)LP*NP*G4];
__device__ __align__(16) float g_gpre_pb[(size_t)LP*NP*G4];
__device__ __align__(16) float g_hpf[(size_t)LP*NP*H];
__device__ __align__(16) float g_hpb[(size_t)LP*NP*H];
__device__ __align__(16) float g_cpf[NP*H];
__device__ __align__(16) float g_cpb[NP*H];
__device__ __align__(16) float g_hcatp[(size_t)LP*NP*2*H];
__device__ __align__(16) float g_zero[NU*H];   // zero-initialized, never written

__device__ __forceinline__ float sigm(float x) { return 1.f / (1.f + expf(-x)); }

// ---------------- prep: token lengths + backward-input row map ----------------
__global__ void prep_tok(const int* __restrict__ units, int* __restrict__ toklen,
                         int* __restrict__ rm_b) {
    int n = blockIdx.x * blockDim.x + threadIdx.x;
    if (n >= NU) return;
    int len = T_TOK;
    for (int t = 0; t < T_TOK; t++)
        if (units[t*NU + n] == 0) { len = t; break; }
    toklen[n] = len;
    for (int s = 0; s < T_TOK; s++) {
        int st = len - 1 - s;
        st = st < 0 ? 0 : (st > T_TOK-1 ? T_TOK-1 : st);
        rm_b[s*NU + n] = units[st*NU + n];   // emb row id (pad -> row 0, matches ref)
    }
}

// ---------------- prep: path lengths + gather row maps ----------------
__global__ void prep_path(const int* __restrict__ paths, const int* __restrict__ upd,
                          const int* __restrict__ ppd, int* __restrict__ plen_out,
                          int* __restrict__ rm_f, int* __restrict__ rm_b) {
    int p = blockIdx.x * blockDim.x + threadIdx.x;
    if (p >= NP) return;
    int d = 0, cum = 0;
    for (int i = 0; i < 8; i++) { int c = ppd[i]; if (p < cum + c) { d = i; break; } cum += c; }
    int off = 0;
    for (int i = 0; i < d; i++) off += upd[i];
    int un = upd[d];
    int fe = LP;
    for (int l = 0; l < LP; l++)
        if (paths[l*NP + p] == -1) { fe = l; break; }
    int plen = LP;
    for (int l = 0; l < LP; l++) {
        int pv = paths[l*NP + p];
        bool m = (l < fe) ? (pv < 0 || pv > un) : true;
        if (m) { plen = l; break; }
    }
    plen_out[p] = plen;
    for (int l = 0; l < LP; l++) {
        int pv = paths[l*NP + p];
        bool keep = (l < fe) && pv >= 0 && pv < un;
        int pvc = pv < 0 ? 0 : pv;
        int gidx = pvc + off; if (gidx > NU-1) gidx = NU-1;
        rm_f[l*NP + p] = keep ? gidx : -1;
    }
    for (int s = 0; s < LP; s++) {
        int sl = plen - 1 - s;
        sl = sl < 0 ? 0 : (sl > LP-1 ? LP-1 : sl);
        int pv = paths[sl*NP + p];
        bool keep = (sl < fe) && pv >= 0 && pv < un;
        int pvc = pv < 0 ? 0 : pv;
        int gidx = pvc + off; if (gidx > NU-1) gidx = NU-1;
        rm_b[s*NP + p] = keep ? gidx : -1;
    }
}

// ---------------- clear LSTM cell state (graph-replay determinism) ----------------
__global__ void clear_c() {
    int i = blockIdx.x * 256 + threadIdx.x;
    if (i < NU*H) { g_cf[i] = 0.f; g_cb[i] = 0.f; }
    if (i < NP*H) { g_cpf[i] = 0.f; g_cpb[i] = 0.f; }
}

// ---------------- generic GEMM: C[m][n] = bias[n] + sum_k Arow(m)[k] * B[n][k] ----------------
// Arow(m) = rowmap ? (rowmap[m] >= 0 ? A + rowmap[m]*K : zeros) : A + m*K
// BM=BN=128, BK=16, 256 threads, 8x8 per thread. M,N,K all divide evenly here.
__global__ __launch_bounds__(256) void gemm_bias(
    const float* __restrict__ A, const int* __restrict__ rowmap,
    const float* __restrict__ B, const float* __restrict__ bias,
    float* __restrict__ C, int M, int N, int K)
{
    __shared__ __align__(16) float As[16][136];
    __shared__ __align__(16) float Bs[16][136];
    __shared__ int rid[128];
    int tid = threadIdx.x;
    int m0 = blockIdx.y * 128, n0 = blockIdx.x * 128;
    if (tid < 128) rid[tid] = rowmap ? rowmap[m0 + tid] : (m0 + tid);
    int lr = tid >> 1;          // 0..127
    int lk = (tid & 1) * 8;     // 0 or 8
    int tx = tid & 15, ty = tid >> 4;
    float acc[8][8];
#pragma unroll
    for (int i = 0; i < 8; i++)
#pragma unroll
        for (int j = 0; j < 8; j++) acc[i][j] = 0.f;
    __syncthreads();

    for (int k0 = 0; k0 < K; k0 += 16) {
        int r = rid[lr];
        float4 a0, a1;
        if (r >= 0) {
            const float* ap = A + (size_t)r * K + k0 + lk;
            a0 = *(const float4*)ap;
            a1 = *(const float4*)(ap + 4);
        } else {
            a0 = make_float4(0.f,0.f,0.f,0.f);
            a1 = make_float4(0.f,0.f,0.f,0.f);
        }
        const float* bp = B + (size_t)(n0 + lr) * K + k0 + lk;
        float4 b0 = *(const float4*)bp;
        float4 b1 = *(const float4*)(bp + 4);
        As[lk+0][lr]=a0.x; As[lk+1][lr]=a0.y; As[lk+2][lr]=a0.z; As[lk+3][lr]=a0.w;
        As[lk+4][lr]=a1.x; As[lk+5][lr]=a1.y; As[lk+6][lr]=a1.z; As[lk+7][lr]=a1.w;
        Bs[lk+0][lr]=b0.x; Bs[lk+1][lr]=b0.y; Bs[lk+2][lr]=b0.z; Bs[lk+3][lr]=b0.w;
        Bs[lk+4][lr]=b1.x; Bs[lk+5][lr]=b1.y; Bs[lk+6][lr]=b1.z; Bs[lk+7][lr]=b1.w;
        __syncthreads();
#pragma unroll
        for (int k = 0; k < 16; k++) {
            float4 av0 = *(const float4*)&As[k][ty*8];
            float4 av1 = *(const float4*)&As[k][ty*8+4];
            float4 bv0 = *(const float4*)&Bs[k][tx*8];
            float4 bv1 = *(const float4*)&Bs[k][tx*8+4];
            float am[8] = {av0.x,av0.y,av0.z,av0.w,av1.x,av1.y,av1.z,av1.w};
            float bn[8] = {bv0.x,bv0.y,bv0.z,bv0.w,bv1.x,bv1.y,bv1.z,bv1.w};
#pragma unroll
            for (int i = 0; i < 8; i++)
#pragma unroll
                for (int j = 0; j < 8; j++) acc[i][j] += am[i] * bn[j];
        }
        __syncthreads();
    }
    float bs[8];
#pragma unroll
    for (int j = 0; j < 8; j++) bs[j] = bias[n0 + tx*8 + j];
#pragma unroll
    for (int i = 0; i < 8; i++) {
        float* crow = C + (size_t)(m0 + ty*8 + i) * N + n0 + tx*8;
        float4 v0 = make_float4(acc[i][0]+bs[0], acc[i][1]+bs[1], acc[i][2]+bs[2], acc[i][3]+bs[3]);
        float4 v1 = make_float4(acc[i][4]+bs[4], acc[i][5]+bs[5], acc[i][6]+bs[6], acc[i][7]+bs[7]);
        *(float4*)crow = v0;
        *(float4*)(crow + 4) = v1;
    }
}

// ---------------- fused LSTM step: gates = gpre + h_prev@Wh^T, then cell update ----------------
struct StepArgs {
    const float* gpre;    // [batch*512] for this step
    const float* h_prev;  // [batch*128]
    float*       h_out;   // [batch*128]
    float*       c;       // [batch*128]
    const float* Wh;      // [512*128]
};

// block: 256 thr = 8 warps; warp w handles 4 units, lanes = 32 cells (blockIdx.y quadrant)
// grid: (batch/32, 4, 2) ; z selects direction
__global__ __launch_bounds__(256) void lstm_step(StepArgs A0, StepArgs A1) {
    StepArgs a = blockIdx.z ? A1 : A0;
    int warp = threadIdx.x >> 5, lane = threadIdx.x & 31;
    int nblk = blockIdx.x * 32;
    int j0 = blockIdx.y * 32;
    __shared__ float Ws[4][32][33];
    __shared__ float Hs[32][32];
    float acc[4][4];
#pragma unroll
    for (int u = 0; u < 4; u++)
#pragma unroll
        for (int q = 0; q < 4; q++) acc[u][q] = 0.f;

    for (int kc = 0; kc < 128; kc += 32) {
        for (int i = threadIdx.x; i < 32*32; i += 256) {
            int nn = i >> 5, k = i & 31;
            Hs[nn][k] = a.h_prev[(size_t)(nblk + nn)*128 + kc + k];
        }
        for (int i = threadIdx.x; i < 4*32*32; i += 256) {
            int q = i >> 10, cc = (i >> 5) & 31, k = i & 31;
            Ws[q][cc][k] = a.Wh[(size_t)(q*128 + j0 + cc)*128 + kc + k];
        }
        __syncthreads();
#pragma unroll
        for (int k = 0; k < 32; k++) {
            float w0 = Ws[0][lane][k], w1 = Ws[1][lane][k];
            float w2 = Ws[2][lane][k], w3 = Ws[3][lane][k];
#pragma unroll
            for (int u = 0; u < 4; u++) {
                float hv = Hs[warp*4 + u][k];
                acc[u][0] += hv * w0; acc[u][1] += hv * w1;
                acc[u][2] += hv * w2; acc[u][3] += hv * w3;
            }
        }
        __syncthreads();
    }
    int j = j0 + lane;
#pragma unroll
    for (int u = 0; u < 4; u++) {
        int n = nblk + warp*4 + u;
        const float* gp = a.gpre + (size_t)n * 512;
        float gi = gp[j      ] + acc[u][0];
        float gf = gp[j + 128] + acc[u][1];
        float gg = gp[j + 256] + acc[u][2];
        float go = gp[j + 384] + acc[u][3];
        size_t ix = (size_t)n * 128 + j;
        float cn = sigm(gf) * a.c[ix] + sigm(gi) * tanhf(gg);
        float hn = sigm(go) * tanhf(cn);
        a.c[ix] = cn;
        a.h_out[ix] = hn;
    }
}

// ---------------- concat fwd/bwd hidden states with validity mask + bwd time-gather ----------------
__global__ void hcat_tok(const float* __restrict__ hf, const float* __restrict__ hb,
                         const int* __restrict__ toklen, float* __restrict__ hcat) {
    size_t idx = (size_t)blockIdx.x * 256 + threadIdx.x;   // over T_TOK*NU*H
    int k = (int)(idx & 127);
    size_t row = idx >> 7;
    int n = (int)(row & (NU-1));
    int t = (int)(row >> 12);
    int len = toklen[n];
    bool valid = t < len;
    int rev = len - 1 - t;
    rev = rev < 0 ? 0 : (rev > T_TOK-1 ? T_TOK-1 : rev);
    float vf = valid ? hf[idx] : 0.f;
    float vb = valid ? hb[((size_t)(rev*NU + n))*128 + k] : 0.f;
    hcat[row*256 + k]       = vf;
    hcat[row*256 + 128 + k] = vb;
}

__global__ void hcat_path(const float* __restrict__ hpf, const float* __restrict__ hpb,
                          const int* __restrict__ plen, float* __restrict__ hcatp) {
    size_t idx = (size_t)blockIdx.x * 256 + threadIdx.x;   // over LP*NP*H
    int k = (int)(idx & 127);
    size_t row = idx >> 7;
    int p = (int)(row & (NP-1));
    int l = (int)(row >> 10);
    int pl = plen[p];
    bool valid = l < pl;
    int rev = pl - 1 - l;
    rev = rev < 0 ? 0 : (rev > LP-1 ? LP-1 : rev);
    float vf = valid ? hpf[idx] : 0.f;
    float vb = valid ? hpb[((size_t)(rev*NP + p))*128 + k] : 0.f;
    hcatp[row*256 + k]       = vf;
    hcatp[row*256 + 128 + k] = vb;
}

// ---------------- attention: LN + tanh + score + masked softmax over t + pooled feature ----------------
__device__ __forceinline__ float blk_sum128(float v, float* r4) {
#pragma unroll
    for (int o = 16; o > 0; o >>= 1) v += __shfl_xor_sync(0xffffffffu, v, o);
    __syncthreads();
    if ((threadIdx.x & 31) == 0) r4[threadIdx.x >> 5] = v;
    __syncthreads();
    return r4[0] + r4[1] + r4[2] + r4[3];
}

__global__ void attn_kernel(const float* __restrict__ outlin, const int* __restrict__ toklen,
                            const float* __restrict__ ln_g, const float* __restrict__ ln_b,
                            const float* __restrict__ attn_w, const float* __restrict__ attn_b,
                            float* __restrict__ tokfeat) {
    int n = blockIdx.x, e = threadIdx.x;
    __shared__ float r4[4];
    __shared__ float sc[T_TOK];
    int len = toklen[n];
    float g = ln_g[e], bb = ln_b[e], aw = attn_w[e], ab = attn_b[0];
    float xv[T_TOK];
    for (int t = 0; t < T_TOK; t++) {
        float x = outlin[((size_t)(t*NU + n))*128 + e];
        xv[t] = x;
        float m = blk_sum128(x, r4) * (1.f/128.f);
        float d = x - m;
        float v = blk_sum128(d*d, r4) * (1.f/128.f);
        float q = tanhf(d * rsqrtf(v + 1e-5f) * g + bb);
        float s = blk_sum128(q * aw, r4);
        if (e == 0) sc[t] = (t < len) ? (s + ab) : -1e9f;
    }
    __syncthreads();
    float mx = -3.4e38f;
#pragma unroll
    for (int t = 0; t < T_TOK; t++) mx = fmaxf(mx, sc[t]);
    float ww[T_TOK]; float den = 0.f;
#pragma unroll
    for (int t = 0; t < T_TOK; t++) { ww[t] = expf(sc[t] - mx); den += ww[t]; }
    float inv = 1.f / den;
    float acc = 0.f;
#pragma unroll
    for (int t = 0; t < T_TOK; t++) acc += ww[t] * inv * xv[t];
    tokfeat[(size_t)n*128 + e] = acc;
}

// ---------------- host ----------------
extern "C" void kernel_launch(void* const* d_in, const int* in_sizes, int n_in,
                              void* d_out, int out_size) {
    const int*   units   = (const int*)d_in[0];
    const int*   paths   = (const int*)d_in[1];
    const int*   upd     = (const int*)d_in[2];
    const int*   ppd     = (const int*)d_in[3];
    const float* emb     = (const float*)d_in[4];
    const float* tl_Wif  = (const float*)d_in[5];
    const float* tl_Whf  = (const float*)d_in[6];
    const float* tl_bf   = (const float*)d_in[7];
    const float* tl_Wib  = (const float*)d_in[8];
    const float* tl_Whb  = (const float*)d_in[9];
    const float* tl_bb   = (const float*)d_in[10];
    const float* lin_W   = (const float*)d_in[11];
    const float* lin_b   = (const float*)d_in[12];
    const float* ln_g    = (const float*)d_in[13];
    const float* ln_bb   = (const float*)d_in[14];
    const float* attn_w  = (const float*)d_in[15];
    const float* attn_b  = (const float*)d_in[16];
    const float* pl_Wif  = (const float*)d_in[17];
    const float* pl_Whf  = (const float*)d_in[18];
    const float* pl_bf   = (const float*)d_in[19];
    const float* pl_Wib  = (const float*)d_in[20];
    const float* pl_Whb  = (const float*)d_in[21];
    const float* pl_bb   = (const float*)d_in[22];
    const float* ul_W    = (const float*)d_in[23];
    const float* ul_b    = (const float*)d_in[24];
    float* out = (float*)d_out;

    float *gpre_f, *gpre_b, *hf, *hb, *cf, *cb, *hcat, *outlin, *tokfeat;
    float *gpre_pf, *gpre_pb, *hpf, *hpb, *cpf, *cpb, *hcatp, *zero;
    int *toklen, *rm_tb, *rm_pf, *rm_pb, *plen;
    cudaGetSymbolAddress((void**)&gpre_f,  g_gpre_f);
    cudaGetSymbolAddress((void**)&gpre_b,  g_gpre_b);
    cudaGetSymbolAddress((void**)&hf,      g_hf);
    cudaGetSymbolAddress((void**)&hb,      g_hb);
    cudaGetSymbolAddress((void**)&cf,      g_cf);
    cudaGetSymbolAddress((void**)&cb,      g_cb);
    cudaGetSymbolAddress((void**)&hcat,    g_hcat);
    cudaGetSymbolAddress((void**)&outlin,  g_outlin);
    cudaGetSymbolAddress((void**)&tokfeat, g_tokfeat);
    cudaGetSymbolAddress((void**)&gpre_pf, g_gpre_pf);
    cudaGetSymbolAddress((void**)&gpre_pb, g_gpre_pb);
    cudaGetSymbolAddress((void**)&hpf,     g_hpf);
    cudaGetSymbolAddress((void**)&hpb,     g_hpb);
    cudaGetSymbolAddress((void**)&cpf,     g_cpf);
    cudaGetSymbolAddress((void**)&cpb,     g_cpb);
    cudaGetSymbolAddress((void**)&hcatp,   g_hcatp);
    cudaGetSymbolAddress((void**)&zero,    g_zero);
    cudaGetSymbolAddress((void**)&toklen,  g_toklen);
    cudaGetSymbolAddress((void**)&rm_tb,   g_rm_tb);
    cudaGetSymbolAddress((void**)&rm_pf,   g_rm_pf);
    cudaGetSymbolAddress((void**)&rm_pb,   g_rm_pb);
    cudaGetSymbolAddress((void**)&plen,    g_plen);

    prep_tok<<<(NU+255)/256, 256>>>(units, toklen, rm_tb);
    clear_c<<<(NU*H+255)/256, 256>>>();

    // token input-gate GEMMs (gathered A = embedding rows)
    gemm_bias<<<dim3(G4/128, T_TOK*NU/128), 256>>>(emb, units, tl_Wif, tl_bf, gpre_f, T_TOK*NU, G4, E);
    gemm_bias<<<dim3(G4/128, T_TOK*NU/128), 256>>>(emb, rm_tb, tl_Wib, tl_bb, gpre_b, T_TOK*NU, G4, E);

    // token recurrent steps (fwd + bwd fused via grid.z)
    for (int t = 0; t < T_TOK; t++) {
        StepArgs af { gpre_f + (size_t)t*NU*G4, t ? hf + (size_t)(t-1)*NU*H : zero,
                      hf + (size_t)t*NU*H, cf, tl_Whf };
        StepArgs ab { gpre_b + (size_t)t*NU*G4, t ? hb + (size_t)(t-1)*NU*H : zero,
                      hb + (size_t)t*NU*H, cb, tl_Whb };
        lstm_step<<<dim3(NU/32, 4, 2), 256>>>(af, ab);
    }

    hcat_tok<<<(int)((size_t)T_TOK*NU*H/256), 256>>>(hf, hb, toklen, hcat);
    gemm_bias<<<dim3(1, T_TOK*NU/128), 256>>>(hcat, nullptr, lin_W, lin_b, outlin, T_TOK*NU, E, 2*H);
    attn_kernel<<<NU, 128>>>(outlin, toklen, ln_g, ln_bb, attn_w, attn_b, tokfeat);

    // path side
    prep_path<<<(NP+255)/256, 256>>>(paths, upd, ppd, plen, rm_pf, rm_pb);
    gemm_bias<<<dim3(G4/128, LP*NP/128), 256>>>(tokfeat, rm_pf, pl_Wif, pl_bf, gpre_pf, LP*NP, G4, E);
    gemm_bias<<<dim3(G4/128, LP*NP/128), 256>>>(tokfeat, rm_pb, pl_Wib, pl_bb, gpre_pb, LP*NP, G4, E);

    for (int s = 0; s < LP; s++) {
        StepArgs af { gpre_pf + (size_t)s*NP*G4, s ? hpf + (size_t)(s-1)*NP*H : zero,
                      hpf + (size_t)s*NP*H, cpf, pl_Whf };
        StepArgs ab { gpre_pb + (size_t)s*NP*G4, s ? hpb + (size_t)(s-1)*NP*H : zero,
                      hpb + (size_t)s*NP*H, cpb, pl_Whb };
        lstm_step<<<dim3(NP/32, 4, 2), 256>>>(af, ab);
    }

    hcat_path<<<(int)((size_t)LP*NP*H/256), 256>>>(hpf, hpb, plen, hcatp);
    gemm_bias<<<dim3(1, LP*NP/128), 256>>>(hcatp, nullptr, ul_W, ul_b, out, LP*NP, E, 2*H);
}